// round 4
// baseline (speedup 1.0000x reference)
#include <cuda_runtime.h>
#include <math.h>
#include <stdint.h>

// Problem constants (fixed by the dataset)
#define U_   2048
#define I_   16384
#define NN_  18432
#define F_   64
#define H_   32
#define EMAX 1000000
#define TOPK_ 3
#define KW   128    // per-warp smem edge staging capacity in k_pairs

// ---------------- device scratch (static globals; no dynamic alloc) -------
__device__ int   g_cnt_u[U_];
__device__ int   g_cnt_i[I_];
__device__ int   g_cursor[I_];
__device__ int   g_off[I_ + 1];
__device__ float g_du[U_];
__device__ float g_di[I_];
__device__ float g_Dh[U_];
__device__ float g_Pu[U_ * H_];
__device__ float g_Pi[I_ * H_];
__device__ uint2 g_csr[EMAX];          // {user, float_bits(weight)} grouped by item
__device__ float g_C[U_ * U_];         // unordered-pair accumulation (one triangle)
__device__ float g_diag[U_];           // sum of w^2 terms per user

// ---------------- kernel 1: zero everything that needs zeroing ------------
__global__ void k_zero(float* __restrict__ outS) {
    int idx = blockIdx.x * blockDim.x + threadIdx.x;
    int stride = gridDim.x * blockDim.x;
    float4 z = make_float4(0.f, 0.f, 0.f, 0.f);
    float4* C4 = (float4*)g_C;
    float4* O4 = (float4*)outS;
    const int n4 = (U_ * U_) / 4;
    for (int i = idx; i < n4; i += stride) { C4[i] = z; O4[i] = z; }
    for (int i = idx; i < I_; i += stride) { g_cnt_i[i] = 0; g_cursor[i] = 0; }
    if (idx < U_) { g_cnt_u[idx] = 0; g_diag[idx] = 0.0f; }
}

// ---------------- kernel 2: degree histograms ------------------------------
__global__ void k_degree(const int* __restrict__ src, const int* __restrict__ dst, int E) {
    int e = blockIdx.x * blockDim.x + threadIdx.x;
    if (e < E) {
        atomicAdd(&g_cnt_u[src[e]], 1);
        atomicAdd(&g_cnt_i[dst[e]], 1);
    }
}

// ---------------- kernel 3: fused scan + log1p degrees (1 block, 1024 thr) -
__global__ void k_scan_findeg(float* __restrict__ out_du, int write_du) {
    __shared__ int wsum[32];
    int t = threadIdx.x;
    int lane = t & 31, wid = t >> 5;
    const int PER = I_ / 1024;           // 16
    int base = t * PER;
    int loc[PER];
    int s = 0;
    #pragma unroll
    for (int j = 0; j < PER; j++) {
        int c = g_cnt_i[base + j];
        loc[j] = s;
        s += c;
        g_di[base + j] = log1pf((float)c);
    }
    int v = s;
    #pragma unroll
    for (int off = 1; off < 32; off <<= 1) {
        int u = __shfl_up_sync(0xffffffffu, v, off);
        if (lane >= off) v += u;
    }
    if (lane == 31) wsum[wid] = v;
    __syncthreads();
    if (wid == 0) {
        int wv = wsum[lane];
        #pragma unroll
        for (int off = 1; off < 32; off <<= 1) {
            int u = __shfl_up_sync(0xffffffffu, wv, off);
            if (lane >= off) wv += u;
        }
        wsum[lane] = wv;
    }
    __syncthreads();
    int prefix = (v - s) + (wid ? wsum[wid - 1] : 0);
    #pragma unroll
    for (int j = 0; j < PER; j++) g_off[base + j] = prefix + loc[j];
    if (t == 1023) g_off[I_] = prefix + s;

    for (int i = t; i < U_; i += 1024) {
        float du = log1pf((float)g_cnt_u[i]);
        g_du[i] = du;
        g_Dh[i] = sqrtf(du);
        if (write_du) out_du[i] = du;
    }
}

// ---------------- kernel 4: per-node projections through w1 ----------------
// Block = 256 threads = 8 warps; each warp computes 4 nodes (32 nodes/block).
// W staged transposed [f][h] in smem; 4 independent accumulators per lane.
__global__ void k_proj(const float* __restrict__ x, const float* __restrict__ w1,
                       const float* __restrict__ b1) {
    __shared__ float swu[65 * 32];   // user cols: f 0..63 + degree col
    __shared__ float swi[65 * 32];   // item cols
    __shared__ float sb1[32];
    __shared__ float sx[32][64];
    for (int i = threadIdx.x; i < 65 * 32; i += 256) {
        int f = i >> 5, h = i & 31;
        swu[i] = w1[h * 130 + f];
        swi[i] = w1[h * 130 + 65 + f];
    }
    if (threadIdx.x < 32) sb1[threadIdx.x] = b1[threadIdx.x];
    int nb0 = blockIdx.x * 32;
    for (int i = threadIdx.x; i < 32 * 64; i += 256) {
        int node = nb0 + (i >> 6);
        sx[i >> 6][i & 63] = x[(size_t)node * F_ + (i & 63)];
    }
    __syncthreads();
    int warp = threadIdx.x >> 5, lane = threadIdx.x & 31;
    int n0 = nb0 + warp * 4;                 // 4 nodes, never straddles U_ boundary
    bool is_user = (n0 < U_);
    const float* W = is_user ? swu : swi;
    const float* x0 = sx[warp * 4 + 0];
    const float* x1 = sx[warp * 4 + 1];
    const float* x2 = sx[warp * 4 + 2];
    const float* x3 = sx[warp * 4 + 3];
    float a0 = 0.f, a1 = 0.f, a2 = 0.f, a3 = 0.f;
    #pragma unroll
    for (int f = 0; f < F_; f++) {
        float w = W[f * 32 + lane];
        a0 = fmaf(x0[f], w, a0);
        a1 = fmaf(x1[f], w, a1);
        a2 = fmaf(x2[f], w, a2);
        a3 = fmaf(x3[f], w, a3);
    }
    float wd = W[64 * 32 + lane];
    if (is_user) {
        float b = sb1[lane];
        g_Pu[(n0 + 0) * H_ + lane] = a0 + g_du[n0 + 0] * wd + b;
        g_Pu[(n0 + 1) * H_ + lane] = a1 + g_du[n0 + 1] * wd + b;
        g_Pu[(n0 + 2) * H_ + lane] = a2 + g_du[n0 + 2] * wd + b;
        g_Pu[(n0 + 3) * H_ + lane] = a3 + g_du[n0 + 3] * wd + b;
    } else {
        int i0 = n0 - U_;
        g_Pi[(i0 + 0) * H_ + lane] = a0 + g_di[i0 + 0] * wd;
        g_Pi[(i0 + 1) * H_ + lane] = a1 + g_di[i0 + 1] * wd;
        g_Pi[(i0 + 2) * H_ + lane] = a2 + g_di[i0 + 2] * wd;
        g_Pi[(i0 + 3) * H_ + lane] = a3 + g_di[i0 + 3] * wd;
    }
}

// ---------------- kernel 5: per-edge weight + CSR scatter -------------------
__global__ void k_edge(const int* __restrict__ src, const int* __restrict__ dst,
                       const float* __restrict__ w2, const float* __restrict__ b2, int E) {
    __shared__ float sw2[H_];
    __shared__ float sb2;
    if (threadIdx.x < H_) sw2[threadIdx.x] = w2[threadIdx.x];
    if (threadIdx.x == 0) sb2 = b2[0];
    __syncthreads();
    int e = blockIdx.x * blockDim.x + threadIdx.x;
    if (e >= E) return;
    int u  = src[e];
    int it = dst[e];
    const float4* pu = (const float4*)(g_Pu + (size_t)u * H_);
    const float4* pi = (const float4*)(g_Pi + (size_t)it * H_);
    float s = 0.0f;
    #pragma unroll
    for (int j = 0; j < H_ / 4; j++) {
        float4 a = pu[j];
        float4 b = pi[j];
        s = fmaf(fmaxf(a.x + b.x, 0.0f), sw2[4 * j + 0], s);
        s = fmaf(fmaxf(a.y + b.y, 0.0f), sw2[4 * j + 1], s);
        s = fmaf(fmaxf(a.z + b.z, 0.0f), sw2[4 * j + 2], s);
        s = fmaf(fmaxf(a.w + b.w, 0.0f), sw2[4 * j + 3], s);
    }
    float w = 1.0f / (1.0f + expf(-(s + sb2)));
    int pos = g_off[it] + atomicAdd(&g_cursor[it], 1);
    if (pos < EMAX) g_csr[pos] = make_uint2((unsigned)u, __float_as_uint(w));
}

// ---------------- kernel 6: pair products, warp-per-item, rotation tiles ---
// Each warp owns one item. Edges staged to per-warp smem. For each 32-edge
// chunk: lane holds b-edge in registers; cross-chunk pairs (a < cb) via
// broadcast LDS sweep (full utilization); intra-chunk pairs via 16 rotation
// steps generating each unordered pair exactly once. Each unordered index
// pair contributes once to C in an arbitrary orientation (k_topk sums both).
__global__ void k_pairs() {
    __shared__ uint2 se[8][KW];
    int warp = threadIdx.x >> 5, lane = threadIdx.x & 31;
    int item = blockIdx.x * 8 + warp;
    if (item >= I_) return;
    int base = g_off[item];
    int k = g_off[item + 1] - base;
    if (k <= 0) return;

    if (k <= KW) {
        uint2* sw = se[warp];
        for (int i = lane; i < k; i += 32) sw[i] = g_csr[base + i];
        __syncwarp();
        for (int cb = 0; cb < k; cb += 32) {
            int bidx = cb + lane;
            bool bval = (bidx < k);
            uint2 eb = sw[bval ? bidx : 0];
            float wb = __uint_as_float(eb.y);
            unsigned ub = eb.x;
            if (bval) atomicAdd(&g_diag[ub], wb * wb);
            float* colbase = g_C + ub;
            // cross-chunk rectangle: a in [0, cb)  (cb is a multiple of 32)
            for (int a = 0; a < cb; a += 4) {
                uint2 e0 = sw[a + 0];
                uint2 e1 = sw[a + 1];
                uint2 e2 = sw[a + 2];
                uint2 e3 = sw[a + 3];
                if (bval) {
                    atomicAdd(colbase + (size_t)e0.x * U_, __uint_as_float(e0.y) * wb);
                    atomicAdd(colbase + (size_t)e1.x * U_, __uint_as_float(e1.y) * wb);
                    atomicAdd(colbase + (size_t)e2.x * U_, __uint_as_float(e2.y) * wb);
                    atomicAdd(colbase + (size_t)e3.x * U_, __uint_as_float(e3.y) * wb);
                }
            }
            // intra-chunk triangle: rotation schedule, each pair exactly once
            #pragma unroll
            for (int s = 1; s <= 16; s++) {
                int pl = (lane + s) & 31;
                unsigned pu = __shfl_sync(0xffffffffu, ub, pl);
                float    pw = __shfl_sync(0xffffffffu, wb, pl);
                bool pval = bval && (cb + pl < k) && (s < 16 || lane < 16);
                if (pval) atomicAdd(&g_C[(size_t)ub * U_ + pu], wb * pw);
            }
        }
    } else {
        // safety fallback (k > KW should not occur for this dataset)
        for (int a = 0; a < k; a++) {
            uint2 ea = g_csr[base + a];
            float wa = __uint_as_float(ea.y);
            if (lane == 0) atomicAdd(&g_diag[ea.x], wa * wa);
            float* Crow = g_C + (size_t)ea.x * U_;
            for (int b = a + 1 + lane; b < k; b += 32) {
                uint2 eb = g_csr[base + b];
                atomicAdd(&Crow[eb.x], wa * __uint_as_float(eb.y));
            }
        }
    }
}

// ---------------- kernel 7: fused sym + scale + top-3 + scatter S ----------
// Block (32,8): 8 rows per block, 256 blocks. Row reads coalesced; column
// reads sector-exact (8 consecutive floats = one 32B sector) via smem tile.
__device__ __forceinline__ bool better(float v, int i, float bv, int bi) {
    return (v > bv) || (v == bv && (unsigned)i < (unsigned)bi);
}
__device__ __forceinline__ void ins3(float v, int i,
                                     float& v0, int& i0, float& v1, int& i1,
                                     float& v2, int& i2) {
    if (better(v, i, v0, i0)) { v2 = v1; i2 = i1; v1 = v0; i1 = i0; v0 = v; i0 = i; }
    else if (better(v, i, v1, i1)) { v2 = v1; i2 = i1; v1 = v; i1 = i; }
    else if (better(v, i, v2, i2)) { v2 = v; i2 = i; }
}

__global__ void k_topk(float* __restrict__ outS) {
    __shared__ float sDh[U_];            // 8 KB
    __shared__ float sB[32][9];          // transposed tile: sB[c_local][r_local]
    int tx = threadIdx.x, ty = threadIdx.y;     // (32,8)
    int tid = ty * 32 + tx;
    for (int i = tid; i < U_; i += 256) sDh[i] = g_Dh[i];
    __syncthreads();
    int r0 = blockIdx.x * 8;
    int r = r0 + ty;
    float dhr = sDh[r];
    float dg = g_diag[r];
    float v0 = -1.0f, v1 = -1.0f, v2 = -1.0f;
    int   i0 = -1,    i1 = -1,    i2 = -1;
    int li = tid >> 3, lj = tid & 7;     // load coords for transposed tile
    for (int c0 = 0; c0 < U_; c0 += 32) {
        sB[li][lj] = g_C[(size_t)(c0 + li) * U_ + (r0 + lj)];
        __syncthreads();
        int c = c0 + tx;
        float v = g_C[(size_t)r * U_ + c] + sB[tx][ty];   // C[r,c] + C[c,r]
        if (c == r) v += dg;
        v *= dhr * sDh[c];
        if (v > 0.0f) ins3(v, c, v0, i0, v1, i1, v2, i2);
        __syncthreads();
    }
    // merge across the 32 lanes of this row's warp
    #pragma unroll
    for (int off = 16; off > 0; off >>= 1) {
        float ov0 = __shfl_down_sync(0xffffffffu, v0, off);
        float ov1 = __shfl_down_sync(0xffffffffu, v1, off);
        float ov2 = __shfl_down_sync(0xffffffffu, v2, off);
        int   oi0 = __shfl_down_sync(0xffffffffu, i0, off);
        int   oi1 = __shfl_down_sync(0xffffffffu, i1, off);
        int   oi2 = __shfl_down_sync(0xffffffffu, i2, off);
        if (ov0 > 0.0f) ins3(ov0, oi0, v0, i0, v1, i1, v2, i2);
        if (ov1 > 0.0f) ins3(ov1, oi1, v0, i0, v1, i1, v2, i2);
        if (ov2 > 0.0f) ins3(ov2, oi2, v0, i0, v1, i1, v2, i2);
    }
    if (tx == 0) {
        float mv[3] = {v0, v1, v2};
        int   mi[3] = {i0, i1, i2};
        #pragma unroll
        for (int q = 0; q < 3; q++) {
            if (mv[q] > 0.0f) {
                float vh = 0.5f * mv[q];
                atomicAdd(&outS[(size_t)r * U_ + mi[q]], vh);
                atomicAdd(&outS[(size_t)mi[q] * U_ + r], vh);
            }
        }
    }
}

// ---------------------------------------------------------------------------
extern "C" void kernel_launch(void* const* d_in, const int* in_sizes, int n_in,
                              void* d_out, int out_size) {
    const float* x   = (const float*)d_in[0];
    const float* w1  = (const float*)d_in[1];
    const float* b1  = (const float*)d_in[2];
    const float* w2  = (const float*)d_in[3];
    const float* b2  = (const float*)d_in[4];
    const int*   src = (const int*)d_in[5];
    const int*   dst = (const int*)d_in[6];
    int E = in_sizes[5];
    if (E > EMAX) E = EMAX;

    float* outS = (float*)d_out;
    int write_du = (out_size >= U_ * U_ + U_) ? 1 : 0;

    k_zero<<<1024, 256>>>(outS);
    k_degree<<<(E + 255) / 256, 256>>>(src, dst, E);
    k_scan_findeg<<<1, 1024>>>(outS + (size_t)U_ * U_, write_du);
    k_proj<<<NN_ / 32, 256>>>(x, w1, b1);
    k_edge<<<(E + 255) / 256, 256>>>(src, dst, w2, b2, E);
    k_pairs<<<(I_ + 7) / 8, 256>>>();
    k_topk<<<U_ / 8, dim3(32, 8)>>>(outS);
}

// round 5
// speedup vs baseline: 1.0423x; 1.0423x over previous
#include <cuda_runtime.h>
#include <math.h>
#include <stdint.h>

// Problem constants (fixed by the dataset)
#define U_   2048
#define I_   16384
#define NN_  18432
#define F_   64
#define H_   32
#define EMAX 1000000
#define TOPK_ 3
#define KW   128    // smem edge staging capacity per item in k_pairs

// ---------------- device scratch (static globals; no dynamic alloc) -------
__device__ int   g_cnt_u[U_];
__device__ int   g_cnt_i[I_];
__device__ int   g_cursor[I_];
__device__ int   g_off[I_ + 1];
__device__ float g_du[U_];
__device__ float g_di[I_];
__device__ float g_Dh[U_];
__device__ float g_Pu[U_ * H_];
__device__ float g_Pi[I_ * H_];
__device__ uint2 g_csr[EMAX];          // {user, float_bits(weight)} grouped by item
__device__ float g_C[U_ * U_];         // unordered-pair accumulation (one triangle)
__device__ float g_diag[U_];           // sum of w^2 terms per user

// ---------------- kernel 1: zero everything that needs zeroing ------------
__global__ void k_zero(float* __restrict__ outS) {
    int idx = blockIdx.x * blockDim.x + threadIdx.x;
    int stride = gridDim.x * blockDim.x;
    float4 z = make_float4(0.f, 0.f, 0.f, 0.f);
    float4* C4 = (float4*)g_C;
    float4* O4 = (float4*)outS;
    const int n4 = (U_ * U_) / 4;
    for (int i = idx; i < n4; i += stride) { C4[i] = z; O4[i] = z; }
    for (int i = idx; i < I_; i += stride) { g_cnt_i[i] = 0; g_cursor[i] = 0; }
    if (idx < U_) { g_cnt_u[idx] = 0; g_diag[idx] = 0.0f; }
}

// ---------------- kernel 2: degree histograms ------------------------------
__global__ void k_degree(const int* __restrict__ src, const int* __restrict__ dst, int E) {
    int e = blockIdx.x * blockDim.x + threadIdx.x;
    if (e < E) {
        atomicAdd(&g_cnt_u[src[e]], 1);
        atomicAdd(&g_cnt_i[dst[e]], 1);
    }
}

// ---------------- kernel 3: fused scan + log1p degrees (1 block, 1024 thr) -
__global__ void k_scan_findeg(float* __restrict__ out_du, int write_du) {
    __shared__ int wsum[32];
    int t = threadIdx.x;
    int lane = t & 31, wid = t >> 5;
    const int PER = I_ / 1024;           // 16
    int base = t * PER;
    int loc[PER];
    int s = 0;
    #pragma unroll
    for (int j = 0; j < PER; j++) {
        int c = g_cnt_i[base + j];
        loc[j] = s;
        s += c;
        g_di[base + j] = log1pf((float)c);
    }
    int v = s;
    #pragma unroll
    for (int off = 1; off < 32; off <<= 1) {
        int u = __shfl_up_sync(0xffffffffu, v, off);
        if (lane >= off) v += u;
    }
    if (lane == 31) wsum[wid] = v;
    __syncthreads();
    if (wid == 0) {
        int wv = wsum[lane];
        #pragma unroll
        for (int off = 1; off < 32; off <<= 1) {
            int u = __shfl_up_sync(0xffffffffu, wv, off);
            if (lane >= off) wv += u;
        }
        wsum[lane] = wv;
    }
    __syncthreads();
    int prefix = (v - s) + (wid ? wsum[wid - 1] : 0);
    #pragma unroll
    for (int j = 0; j < PER; j++) g_off[base + j] = prefix + loc[j];
    if (t == 1023) g_off[I_] = prefix + s;

    for (int i = t; i < U_; i += 1024) {
        float du = log1pf((float)g_cnt_u[i]);
        g_du[i] = du;
        g_Dh[i] = sqrtf(du);
        if (write_du) out_du[i] = du;
    }
}

// ---------------- kernel 4: per-node projections through w1 ----------------
// Block = 256 threads = 8 warps; each warp computes 4 nodes (32 nodes/block).
__global__ void k_proj(const float* __restrict__ x, const float* __restrict__ w1,
                       const float* __restrict__ b1) {
    __shared__ float swu[65 * 32];   // user cols: f 0..63 + degree col
    __shared__ float swi[65 * 32];   // item cols
    __shared__ float sb1[32];
    __shared__ float sx[32][64];
    for (int i = threadIdx.x; i < 65 * 32; i += 256) {
        int f = i >> 5, h = i & 31;
        swu[i] = w1[h * 130 + f];
        swi[i] = w1[h * 130 + 65 + f];
    }
    if (threadIdx.x < 32) sb1[threadIdx.x] = b1[threadIdx.x];
    int nb0 = blockIdx.x * 32;
    for (int i = threadIdx.x; i < 32 * 64; i += 256) {
        int node = nb0 + (i >> 6);
        sx[i >> 6][i & 63] = x[(size_t)node * F_ + (i & 63)];
    }
    __syncthreads();
    int warp = threadIdx.x >> 5, lane = threadIdx.x & 31;
    int n0 = nb0 + warp * 4;                 // never straddles the U_ boundary
    bool is_user = (n0 < U_);
    const float* W = is_user ? swu : swi;
    const float* x0 = sx[warp * 4 + 0];
    const float* x1 = sx[warp * 4 + 1];
    const float* x2 = sx[warp * 4 + 2];
    const float* x3 = sx[warp * 4 + 3];
    float a0 = 0.f, a1 = 0.f, a2 = 0.f, a3 = 0.f;
    #pragma unroll
    for (int f = 0; f < F_; f++) {
        float w = W[f * 32 + lane];
        a0 = fmaf(x0[f], w, a0);
        a1 = fmaf(x1[f], w, a1);
        a2 = fmaf(x2[f], w, a2);
        a3 = fmaf(x3[f], w, a3);
    }
    float wd = W[64 * 32 + lane];
    if (is_user) {
        float b = sb1[lane];
        g_Pu[(n0 + 0) * H_ + lane] = a0 + g_du[n0 + 0] * wd + b;
        g_Pu[(n0 + 1) * H_ + lane] = a1 + g_du[n0 + 1] * wd + b;
        g_Pu[(n0 + 2) * H_ + lane] = a2 + g_du[n0 + 2] * wd + b;
        g_Pu[(n0 + 3) * H_ + lane] = a3 + g_du[n0 + 3] * wd + b;
    } else {
        int i0 = n0 - U_;
        g_Pi[(i0 + 0) * H_ + lane] = a0 + g_di[i0 + 0] * wd;
        g_Pi[(i0 + 1) * H_ + lane] = a1 + g_di[i0 + 1] * wd;
        g_Pi[(i0 + 2) * H_ + lane] = a2 + g_di[i0 + 2] * wd;
        g_Pi[(i0 + 3) * H_ + lane] = a3 + g_di[i0 + 3] * wd;
    }
}

// ---------------- kernel 5: per-edge weight + CSR scatter -------------------
__global__ void k_edge(const int* __restrict__ src, const int* __restrict__ dst,
                       const float* __restrict__ w2, const float* __restrict__ b2, int E) {
    __shared__ float sw2[H_];
    __shared__ float sb2;
    if (threadIdx.x < H_) sw2[threadIdx.x] = w2[threadIdx.x];
    if (threadIdx.x == 0) sb2 = b2[0];
    __syncthreads();
    int e = blockIdx.x * blockDim.x + threadIdx.x;
    if (e >= E) return;
    int u  = src[e];
    int it = dst[e];
    const float4* pu = (const float4*)(g_Pu + (size_t)u * H_);
    const float4* pi = (const float4*)(g_Pi + (size_t)it * H_);
    float s = 0.0f;
    #pragma unroll
    for (int j = 0; j < H_ / 4; j++) {
        float4 a = pu[j];
        float4 b = pi[j];
        s = fmaf(fmaxf(a.x + b.x, 0.0f), sw2[4 * j + 0], s);
        s = fmaf(fmaxf(a.y + b.y, 0.0f), sw2[4 * j + 1], s);
        s = fmaf(fmaxf(a.z + b.z, 0.0f), sw2[4 * j + 2], s);
        s = fmaf(fmaxf(a.w + b.w, 0.0f), sw2[4 * j + 3], s);
    }
    float w = 1.0f / (1.0f + expf(-(s + sb2)));
    int pos = g_off[it] + atomicAdd(&g_cursor[it], 1);
    if (pos < EMAX) g_csr[pos] = make_uint2((unsigned)u, __float_as_uint(w));
}

// ---------------- kernel 6: flattened pair enumeration (the hot kernel) ----
// Block = one item (256 threads). The k(k+1)/2 pairs (a<=b), diagonal
// included, are split into 256 contiguous per-thread spans. Each thread
// inverts its span start once via sqrtf, then walks (a,b) incrementally.
// LSU cost per pair: 2 spread LDS.64 + 1 REDG; index math stays on ALU.
__global__ void k_pairs() {
    __shared__ uint2 se[KW];
    int item = blockIdx.x;
    int base = g_off[item];
    int k = g_off[item + 1] - base;
    if (k <= 0) return;
    int t = threadIdx.x;

    if (k <= KW) {
        for (int i = t; i < k; i += 256) se[i] = g_csr[base + i];
        __syncthreads();
        int Ptot = (k * (k + 1)) >> 1;
        int span = (Ptot + 255) >> 8;
        int p = t * span;
        int pend = p + span;
        if (pend > Ptot) pend = Ptot;
        if (p < pend) {
            // invert start index: q counts pairs from the end
            int q = Ptot - 1 - p;
            int m = (int)((sqrtf(8.0f * (float)q + 1.0f) - 1.0f) * 0.5f);
            while ((m + 1) * (m + 2) / 2 <= q) m++;
            while (m * (m + 1) / 2 > q) m--;
            int a = k - 1 - m;
            int b = k - 1 - (q - ((m * (m + 1)) >> 1));
            for (; p < pend; p++) {
                uint2 ea = se[a];
                uint2 eb = se[b];
                float v = __uint_as_float(ea.y) * __uint_as_float(eb.y);
                if (a == b) atomicAdd(&g_diag[ea.x], v);
                else atomicAdd(&g_C[((unsigned)ea.x << 11) + eb.x], v);
                if (++b == k) { a++; b = a; }
            }
        }
    } else {
        // safety fallback (k > KW should not occur for this dataset)
        int warp = t >> 5, lane = t & 31;
        for (int a = warp; a < k; a += 8) {
            uint2 ea = g_csr[base + a];
            float wa = __uint_as_float(ea.y);
            if (lane == 0) atomicAdd(&g_diag[ea.x], wa * wa);
            float* Crow = g_C + ((unsigned)ea.x << 11);
            for (int b = a + 1 + lane; b < k; b += 32) {
                uint2 eb = g_csr[base + b];
                atomicAdd(&Crow[eb.x], wa * __uint_as_float(eb.y));
            }
        }
    }
}

// ---------------- kernel 7: fused sym + scale + top-3 + scatter S ----------
// Block (32,8): 8 rows per block, 256 blocks. Row reads coalesced; column
// reads sector-exact (8 consecutive floats = one 32B sector) via smem tile.
__device__ __forceinline__ bool better(float v, int i, float bv, int bi) {
    return (v > bv) || (v == bv && (unsigned)i < (unsigned)bi);
}
__device__ __forceinline__ void ins3(float v, int i,
                                     float& v0, int& i0, float& v1, int& i1,
                                     float& v2, int& i2) {
    if (better(v, i, v0, i0)) { v2 = v1; i2 = i1; v1 = v0; i1 = i0; v0 = v; i0 = i; }
    else if (better(v, i, v1, i1)) { v2 = v1; i2 = i1; v1 = v; i1 = i; }
    else if (better(v, i, v2, i2)) { v2 = v; i2 = i; }
}

__global__ void k_topk(float* __restrict__ outS) {
    __shared__ float sDh[U_];            // 8 KB
    __shared__ float sB[32][9];          // transposed tile: sB[c_local][r_local]
    int tx = threadIdx.x, ty = threadIdx.y;     // (32,8)
    int tid = ty * 32 + tx;
    for (int i = tid; i < U_; i += 256) sDh[i] = g_Dh[i];
    __syncthreads();
    int r0 = blockIdx.x * 8;
    int r = r0 + ty;
    float dhr = sDh[r];
    float dg = g_diag[r];
    float v0 = -1.0f, v1 = -1.0f, v2 = -1.0f;
    int   i0 = -1,    i1 = -1,    i2 = -1;
    int li = tid >> 3, lj = tid & 7;     // load coords for transposed tile
    for (int c0 = 0; c0 < U_; c0 += 32) {
        sB[li][lj] = g_C[(size_t)(c0 + li) * U_ + (r0 + lj)];
        __syncthreads();
        int c = c0 + tx;
        float v = g_C[(size_t)r * U_ + c] + sB[tx][ty];   // C[r,c] + C[c,r]
        if (c == r) v += dg;
        v *= dhr * sDh[c];
        if (v > 0.0f) ins3(v, c, v0, i0, v1, i1, v2, i2);
        __syncthreads();
    }
    #pragma unroll
    for (int off = 16; off > 0; off >>= 1) {
        float ov0 = __shfl_down_sync(0xffffffffu, v0, off);
        float ov1 = __shfl_down_sync(0xffffffffu, v1, off);
        float ov2 = __shfl_down_sync(0xffffffffu, v2, off);
        int   oi0 = __shfl_down_sync(0xffffffffu, i0, off);
        int   oi1 = __shfl_down_sync(0xffffffffu, i1, off);
        int   oi2 = __shfl_down_sync(0xffffffffu, i2, off);
        if (ov0 > 0.0f) ins3(ov0, oi0, v0, i0, v1, i1, v2, i2);
        if (ov1 > 0.0f) ins3(ov1, oi1, v0, i0, v1, i1, v2, i2);
        if (ov2 > 0.0f) ins3(ov2, oi2, v0, i0, v1, i1, v2, i2);
    }
    if (tx == 0) {
        float mv[3] = {v0, v1, v2};
        int   mi[3] = {i0, i1, i2};
        #pragma unroll
        for (int q = 0; q < 3; q++) {
            if (mv[q] > 0.0f) {
                float vh = 0.5f * mv[q];
                atomicAdd(&outS[(size_t)r * U_ + mi[q]], vh);
                atomicAdd(&outS[(size_t)mi[q] * U_ + r], vh);
            }
        }
    }
}

// ---------------------------------------------------------------------------
extern "C" void kernel_launch(void* const* d_in, const int* in_sizes, int n_in,
                              void* d_out, int out_size) {
    const float* x   = (const float*)d_in[0];
    const float* w1  = (const float*)d_in[1];
    const float* b1  = (const float*)d_in[2];
    const float* w2  = (const float*)d_in[3];
    const float* b2  = (const float*)d_in[4];
    const int*   src = (const int*)d_in[5];
    const int*   dst = (const int*)d_in[6];
    int E = in_sizes[5];
    if (E > EMAX) E = EMAX;

    float* outS = (float*)d_out;
    int write_du = (out_size >= U_ * U_ + U_) ? 1 : 0;

    k_zero<<<1024, 256>>>(outS);
    k_degree<<<(E + 255) / 256, 256>>>(src, dst, E);
    k_scan_findeg<<<1, 1024>>>(outS + (size_t)U_ * U_, write_du);
    k_proj<<<NN_ / 32, 256>>>(x, w1, b1);
    k_edge<<<(E + 255) / 256, 256>>>(src, dst, w2, b2, E);
    k_pairs<<<I_, 256>>>();
    k_topk<<<U_ / 8, dim3(32, 8)>>>(outS);
}

// round 6
// speedup vs baseline: 1.1128x; 1.0676x over previous
#include <cuda_runtime.h>
#include <math.h>
#include <stdint.h>

// Problem constants (fixed by the dataset)
#define U_   2048
#define I_   16384
#define NN_  18432
#define F_   64
#define H_   32
#define EMAX 1000000
#define TOPK_ 3

// ---------------- device scratch (static globals; no dynamic alloc) -------
__device__ int   g_cnt_u[U_];
__device__ int   g_cnt_i[I_];
__device__ int   g_cursor[I_];
__device__ int   g_off[I_ + 1];
__device__ float g_du[U_];
__device__ float g_di[I_];
__device__ float g_Dh[U_];
__device__ float g_Pu[U_ * H_];
__device__ float g_Pi[I_ * H_];
__device__ uint2 g_csr[EMAX];          // {user, float_bits(weight)} grouped by item
__device__ float g_C[U_ * U_];         // unordered-pair accumulation (one triangle)
__device__ float g_diag[U_];           // sum of w^2 terms per user

// ---------------- kernel 1: zero everything that needs zeroing ------------
__global__ void k_zero(float* __restrict__ outS) {
    int idx = blockIdx.x * blockDim.x + threadIdx.x;
    int stride = gridDim.x * blockDim.x;
    float4 z = make_float4(0.f, 0.f, 0.f, 0.f);
    float4* C4 = (float4*)g_C;
    float4* O4 = (float4*)outS;
    const int n4 = (U_ * U_) / 4;
    for (int i = idx; i < n4; i += stride) { C4[i] = z; O4[i] = z; }
    for (int i = idx; i < I_; i += stride) { g_cnt_i[i] = 0; g_cursor[i] = 0; }
    if (idx < U_) { g_cnt_u[idx] = 0; g_diag[idx] = 0.0f; }
}

// ---------------- kernel 2: degree histograms ------------------------------
__global__ void k_degree(const int* __restrict__ src, const int* __restrict__ dst, int E) {
    int e = blockIdx.x * blockDim.x + threadIdx.x;
    if (e < E) {
        atomicAdd(&g_cnt_u[src[e]], 1);
        atomicAdd(&g_cnt_i[dst[e]], 1);
    }
}

// ---------------- kernel 3: fused scan + log1p degrees (1 block, 1024 thr) -
__global__ void k_scan_findeg(float* __restrict__ out_du, int write_du) {
    __shared__ int wsum[32];
    int t = threadIdx.x;
    int lane = t & 31, wid = t >> 5;
    const int PER = I_ / 1024;           // 16
    int base = t * PER;
    int loc[PER];
    int s = 0;
    #pragma unroll
    for (int j = 0; j < PER; j++) {
        int c = g_cnt_i[base + j];
        loc[j] = s;
        s += c;
        g_di[base + j] = log1pf((float)c);
    }
    int v = s;
    #pragma unroll
    for (int off = 1; off < 32; off <<= 1) {
        int u = __shfl_up_sync(0xffffffffu, v, off);
        if (lane >= off) v += u;
    }
    if (lane == 31) wsum[wid] = v;
    __syncthreads();
    if (wid == 0) {
        int wv = wsum[lane];
        #pragma unroll
        for (int off = 1; off < 32; off <<= 1) {
            int u = __shfl_up_sync(0xffffffffu, wv, off);
            if (lane >= off) wv += u;
        }
        wsum[lane] = wv;
    }
    __syncthreads();
    int prefix = (v - s) + (wid ? wsum[wid - 1] : 0);
    #pragma unroll
    for (int j = 0; j < PER; j++) g_off[base + j] = prefix + loc[j];
    if (t == 1023) g_off[I_] = prefix + s;

    for (int i = t; i < U_; i += 1024) {
        float du = log1pf((float)g_cnt_u[i]);
        g_du[i] = du;
        g_Dh[i] = sqrtf(du);
        if (write_du) out_du[i] = du;
    }
}

// ---------------- kernel 4: per-node projections through w1 ----------------
// Block = 256 threads = 8 warps; each warp computes 4 nodes (32 nodes/block).
__global__ void k_proj(const float* __restrict__ x, const float* __restrict__ w1,
                       const float* __restrict__ b1) {
    __shared__ float swu[65 * 32];   // user cols: f 0..63 + degree col
    __shared__ float swi[65 * 32];   // item cols
    __shared__ float sb1[32];
    __shared__ float sx[32][64];
    for (int i = threadIdx.x; i < 65 * 32; i += 256) {
        int f = i >> 5, h = i & 31;
        swu[i] = w1[h * 130 + f];
        swi[i] = w1[h * 130 + 65 + f];
    }
    if (threadIdx.x < 32) sb1[threadIdx.x] = b1[threadIdx.x];
    int nb0 = blockIdx.x * 32;
    for (int i = threadIdx.x; i < 32 * 64; i += 256) {
        int node = nb0 + (i >> 6);
        sx[i >> 6][i & 63] = x[(size_t)node * F_ + (i & 63)];
    }
    __syncthreads();
    int warp = threadIdx.x >> 5, lane = threadIdx.x & 31;
    int n0 = nb0 + warp * 4;                 // never straddles the U_ boundary
    bool is_user = (n0 < U_);
    const float* W = is_user ? swu : swi;
    const float* x0 = sx[warp * 4 + 0];
    const float* x1 = sx[warp * 4 + 1];
    const float* x2 = sx[warp * 4 + 2];
    const float* x3 = sx[warp * 4 + 3];
    float a0 = 0.f, a1 = 0.f, a2 = 0.f, a3 = 0.f;
    #pragma unroll
    for (int f = 0; f < F_; f++) {
        float w = W[f * 32 + lane];
        a0 = fmaf(x0[f], w, a0);
        a1 = fmaf(x1[f], w, a1);
        a2 = fmaf(x2[f], w, a2);
        a3 = fmaf(x3[f], w, a3);
    }
    float wd = W[64 * 32 + lane];
    if (is_user) {
        float b = sb1[lane];
        g_Pu[(n0 + 0) * H_ + lane] = a0 + g_du[n0 + 0] * wd + b;
        g_Pu[(n0 + 1) * H_ + lane] = a1 + g_du[n0 + 1] * wd + b;
        g_Pu[(n0 + 2) * H_ + lane] = a2 + g_du[n0 + 2] * wd + b;
        g_Pu[(n0 + 3) * H_ + lane] = a3 + g_du[n0 + 3] * wd + b;
    } else {
        int i0 = n0 - U_;
        g_Pi[(i0 + 0) * H_ + lane] = a0 + g_di[i0 + 0] * wd;
        g_Pi[(i0 + 1) * H_ + lane] = a1 + g_di[i0 + 1] * wd;
        g_Pi[(i0 + 2) * H_ + lane] = a2 + g_di[i0 + 2] * wd;
        g_Pi[(i0 + 3) * H_ + lane] = a3 + g_di[i0 + 3] * wd;
    }
}

// ---------------- kernel 5: per-edge weight + CSR scatter -------------------
__global__ void k_edge(const int* __restrict__ src, const int* __restrict__ dst,
                       const float* __restrict__ w2, const float* __restrict__ b2, int E) {
    __shared__ float sw2[H_];
    __shared__ float sb2;
    if (threadIdx.x < H_) sw2[threadIdx.x] = w2[threadIdx.x];
    if (threadIdx.x == 0) sb2 = b2[0];
    __syncthreads();
    int e = blockIdx.x * blockDim.x + threadIdx.x;
    if (e >= E) return;
    int u  = src[e];
    int it = dst[e];
    const float4* pu = (const float4*)(g_Pu + (size_t)u * H_);
    const float4* pi = (const float4*)(g_Pi + (size_t)it * H_);
    float s = 0.0f;
    #pragma unroll
    for (int j = 0; j < H_ / 4; j++) {
        float4 a = pu[j];
        float4 b = pi[j];
        s = fmaf(fmaxf(a.x + b.x, 0.0f), sw2[4 * j + 0], s);
        s = fmaf(fmaxf(a.y + b.y, 0.0f), sw2[4 * j + 1], s);
        s = fmaf(fmaxf(a.z + b.z, 0.0f), sw2[4 * j + 2], s);
        s = fmaf(fmaxf(a.w + b.w, 0.0f), sw2[4 * j + 3], s);
    }
    float w = 1.0f / (1.0f + expf(-(s + sb2)));
    int pos = g_off[it] + atomicAdd(&g_cursor[it], 1);
    if (pos < EMAX) g_csr[pos] = make_uint2((unsigned)u, __float_as_uint(w));
}

// ---------------- kernel 6: pair products — R1 schedule, TRANSPOSED target -
// Block = one item. Warp w handles a = w, w+8, ...; lanes sweep b > a.
// KEY CHANGE vs R1: atomic target is C[u_b, u_a] so the 32 lanes of one
// warp-instruction hit 32 DIFFERENT rows (8KB-strided lines -> spread across
// LTS slices) instead of adjacent addresses in one row (slice-serialized).
__global__ void k_pairs() {
    int t = blockIdx.x;
    int base = g_off[t];
    int k = g_off[t + 1] - base;
    if (k <= 0) return;
    int warp = threadIdx.x >> 5;
    int lane = threadIdx.x & 31;
    for (int a = warp; a < k; a += 8) {
        uint2 ea = g_csr[base + a];        // broadcast load
        float wa = __uint_as_float(ea.y);
        if (lane == 0) atomicAdd(&g_diag[ea.x], wa * wa);
        unsigned ua = ea.x;
        for (int b = a + 1 + lane; b < k; b += 32) {
            uint2 eb = g_csr[base + b];
            atomicAdd(&g_C[((unsigned)eb.x << 11) + ua], wa * __uint_as_float(eb.y));
        }
    }
}

// ---------------- kernel 7: sym + scale + top-3 + scatter S (R1 version) ---
__device__ __forceinline__ bool better(float v, int i, float bv, int bi) {
    return (v > bv) || (v == bv && (unsigned)i < (unsigned)bi);
}
__device__ __forceinline__ void ins3(float v, int i,
                                     float& v0, int& i0, float& v1, int& i1,
                                     float& v2, int& i2) {
    if (better(v, i, v0, i0)) { v2 = v1; i2 = i1; v1 = v0; i1 = i0; v0 = v; i0 = i; }
    else if (better(v, i, v1, i1)) { v2 = v1; i2 = i1; v1 = v; i1 = i; }
    else if (better(v, i, v2, i2)) { v2 = v; i2 = i; }
}

__global__ void k_topk(float* __restrict__ outS) {
    __shared__ float svals[256 * 3];
    __shared__ int   sidx[256 * 3];
    int r = blockIdx.x;
    float dhr = g_Dh[r];
    float v0 = -1.0f, v1 = -1.0f, v2 = -1.0f;
    int   i0 = -1,    i1 = -1,    i2 = -1;
    for (int c = threadIdx.x; c < U_; c += blockDim.x) {
        float v = g_C[(size_t)r * U_ + c] + g_C[(size_t)c * U_ + r];
        if (c == r) v += g_diag[r];
        v *= dhr * g_Dh[c];
        if (v > 0.0f) ins3(v, c, v0, i0, v1, i1, v2, i2);
    }
    int t = threadIdx.x;
    svals[t * 3 + 0] = v0; sidx[t * 3 + 0] = i0;
    svals[t * 3 + 1] = v1; sidx[t * 3 + 1] = i1;
    svals[t * 3 + 2] = v2; sidx[t * 3 + 2] = i2;
    __syncthreads();
    if (t < 32) {
        float m0 = -1.0f, m1 = -1.0f, m2 = -1.0f;
        int   j0 = -1,    j1 = -1,    j2 = -1;
        for (int j = t; j < 256; j += 32) {
            #pragma unroll
            for (int q = 0; q < 3; q++) {
                float v = svals[j * 3 + q];
                if (v > 0.0f) ins3(v, sidx[j * 3 + q], m0, j0, m1, j1, m2, j2);
            }
        }
        #pragma unroll
        for (int off = 16; off > 0; off >>= 1) {
            float ov0 = __shfl_down_sync(0xffffffffu, m0, off);
            float ov1 = __shfl_down_sync(0xffffffffu, m1, off);
            float ov2 = __shfl_down_sync(0xffffffffu, m2, off);
            int   oi0 = __shfl_down_sync(0xffffffffu, j0, off);
            int   oi1 = __shfl_down_sync(0xffffffffu, j1, off);
            int   oi2 = __shfl_down_sync(0xffffffffu, j2, off);
            if (ov0 > 0.0f) ins3(ov0, oi0, m0, j0, m1, j1, m2, j2);
            if (ov1 > 0.0f) ins3(ov1, oi1, m0, j0, m1, j1, m2, j2);
            if (ov2 > 0.0f) ins3(ov2, oi2, m0, j0, m1, j1, m2, j2);
        }
        if (t == 0) {
            float mv[3] = {m0, m1, m2};
            int   mi[3] = {j0, j1, j2};
            #pragma unroll
            for (int q = 0; q < 3; q++) {
                if (mv[q] > 0.0f) {
                    float vh = 0.5f * mv[q];
                    atomicAdd(&outS[(size_t)r * U_ + mi[q]], vh);
                    atomicAdd(&outS[(size_t)mi[q] * U_ + r], vh);
                }
            }
        }
    }
}

// ---------------------------------------------------------------------------
extern "C" void kernel_launch(void* const* d_in, const int* in_sizes, int n_in,
                              void* d_out, int out_size) {
    const float* x   = (const float*)d_in[0];
    const float* w1  = (const float*)d_in[1];
    const float* b1  = (const float*)d_in[2];
    const float* w2  = (const float*)d_in[3];
    const float* b2  = (const float*)d_in[4];
    const int*   src = (const int*)d_in[5];
    const int*   dst = (const int*)d_in[6];
    int E = in_sizes[5];
    if (E > EMAX) E = EMAX;

    float* outS = (float*)d_out;
    int write_du = (out_size >= U_ * U_ + U_) ? 1 : 0;

    k_zero<<<1024, 256>>>(outS);
    k_degree<<<(E + 255) / 256, 256>>>(src, dst, E);
    k_scan_findeg<<<1, 1024>>>(outS + (size_t)U_ * U_, write_du);
    k_proj<<<NN_ / 32, 256>>>(x, w1, b1);
    k_edge<<<(E + 255) / 256, 256>>>(src, dst, w2, b2, E);
    k_pairs<<<I_, 256>>>();
    k_topk<<<U_, 256>>>(outS);
}